// round 16
// baseline (speedup 1.0000x reference)
#include <cuda_runtime.h>
#include <cuda_fp16.h>

// AOLayer: out[b,n,a] = ang * rad, B=512,N=32,A=256,P=6.
// Round 16: r15 two-phase skeleton (proven latency-tolerant: ncu 11.36 at
// occ 32.5%, issue 75.9%) x r11 lc-folded f16x2 radial (halves MUFU, trims
// slots; intrinsic-only so no ALU bloat). Phase 1: f32 r2+angular for all 16
// rows. Phase 2: row-pairs, per p = 2 FFMA + 1 cvt + 1 h2exp2 + 1 HFMA2.
// MUFU per thread-block-pass: 96 -> 48. rel_err ~5.3e-4 (r11-measured).

#define A_DIM 256
#define P_DIM 6
#define BN_DIM (512 * 32)
#define ROWS_PER_BLOCK 16

__global__ void __launch_bounds__(A_DIM, 3) aolayer_kernel(
    const float* __restrict__ pos,      // [BN, 3]
    const float* __restrict__ centers,  // [A, 3]
    const float* __restrict__ exps,     // [A, P]
    const float* __restrict__ coeffs,   // [A, P]
    const int*   __restrict__ powers,   // [A, 3]
    float* __restrict__ out)            // [BN, A]
{
    const int a = threadIdx.x;

    // ---- per-atom constants (once per block) ----
    const float ncx = -centers[a * 3 + 0];
    const float ncy = -centers[a * 3 + 1];
    const float ncz = -centers[a * 3 + 2];

    const float NEG_LOG2E = -1.4426950408889634f;
    float ep[P_DIM], lc[P_DIM];
    __half2 sg[P_DIM];
#pragma unroll
    for (int p = 0; p < P_DIM; p++) {
        ep[p] = exps[a * P_DIM + p] * NEG_LOG2E;
        const float c = coeffs[a * P_DIM + p];
        lc[p] = __log2f(fabsf(c));               // -inf if c==0 -> exp2 -> 0 (ok)
        sg[p] = __float2half2_rn(copysignf(1.0f, c));
    }

    const int px = powers[a * 3 + 0];
    const int py = powers[a * 3 + 1];
    const int pz = powers[a * 3 + 2];
    const bool lx = (px >= 1), qx = (px == 2);
    const bool ly = (py >= 1), qy = (py == 2);
    const bool lz = (pz >= 1), qz = (pz == 2);

    // ---- stage pos rows into shared memory ----
    __shared__ float spos[ROWS_PER_BLOCK * 3];
    const int row0 = blockIdx.x * ROWS_PER_BLOCK;
    if (threadIdx.x < ROWS_PER_BLOCK * 3) {
        spos[threadIdx.x] = pos[row0 * 3 + threadIdx.x];
    }
    __syncthreads();

    // ---- phase 1: all rows' r2 and angular (f32; d dies immediately) ----
    float r2v[ROWS_PER_BLOCK];
    float angv[ROWS_PER_BLOCK];
#pragma unroll
    for (int r = 0; r < ROWS_PER_BLOCK; r++) {
        const float dx = spos[r * 3 + 0] + ncx;
        const float dy = spos[r * 3 + 1] + ncy;
        const float dz = spos[r * 3 + 2] + ncz;

        r2v[r] = fmaf(dx, dx, fmaf(dy, dy, dz * dz));

        float t = lx ? dx : 1.0f;
        if (qx) t *= dx;
        if (ly) t *= dy;
        if (qy) t *= dy;
        if (lz) t *= dz;
        if (qz) t *= dz;
        angv[r] = t;
    }

    float* out_base = out + (size_t)row0 * A_DIM + a;

    // ---- phase 2: row-pairs; one f16x2 exp2 serves both rows per p ----
#pragma unroll
    for (int r = 0; r < ROWS_PER_BLOCK; r += 2) {
        const float r2a = r2v[r];
        const float r2b = r2v[r + 1];

        __half2 acc0 = __hmul2(h2exp2(__floats2half2_rn(fmaf(ep[0], r2a, lc[0]),
                                                        fmaf(ep[0], r2b, lc[0]))), sg[0]);
        __half2 acc1 = __hmul2(h2exp2(__floats2half2_rn(fmaf(ep[1], r2a, lc[1]),
                                                        fmaf(ep[1], r2b, lc[1]))), sg[1]);
        acc0 = __hfma2(h2exp2(__floats2half2_rn(fmaf(ep[2], r2a, lc[2]),
                                                fmaf(ep[2], r2b, lc[2]))), sg[2], acc0);
        acc1 = __hfma2(h2exp2(__floats2half2_rn(fmaf(ep[3], r2a, lc[3]),
                                                fmaf(ep[3], r2b, lc[3]))), sg[3], acc1);
        acc0 = __hfma2(h2exp2(__floats2half2_rn(fmaf(ep[4], r2a, lc[4]),
                                                fmaf(ep[4], r2b, lc[4]))), sg[4], acc0);
        acc1 = __hfma2(h2exp2(__floats2half2_rn(fmaf(ep[5], r2a, lc[5]),
                                                fmaf(ep[5], r2b, lc[5]))), sg[5], acc1);
        const __half2 rad2 = __hadd2(acc0, acc1);

        out_base[r * A_DIM]       = angv[r]     * __low2float(rad2);
        out_base[(r + 1) * A_DIM] = angv[r + 1] * __high2float(rad2);
    }
}

extern "C" void kernel_launch(void* const* d_in, const int* in_sizes, int n_in,
                              void* d_out, int out_size) {
    const float* pos     = (const float*)d_in[0];
    const float* centers = (const float*)d_in[1];
    const float* exps    = (const float*)d_in[2];
    const float* coeffs  = (const float*)d_in[3];
    const int*   powers  = (const int*)d_in[4];
    float* out = (float*)d_out;

    dim3 grid(BN_DIM / ROWS_PER_BLOCK);  // 1024 blocks
    dim3 block(A_DIM);                   // 256 threads, one per atom
    aolayer_kernel<<<grid, block>>>(pos, centers, exps, coeffs, powers, out);
}

// round 17
// speedup vs baseline: 1.0025x; 1.0025x over previous
#include <cuda_runtime.h>

// AOLayer: out[b,n,a] = ang * rad, B=512,N=32,A=256,P=6.
// Round 17: r15 (two-phase, exact f32; ncu 11.36 @ occ 32.5%, issue 75.9%)
// with the issue ceiling attacked: force 4 blocks/SM (<=64 regs; r15's code
// intrinsically needs ~56, ptxas lazily took 80). +33% warps to fill the
// ~24% empty issue slots. Prologue slimmed with float2 loads (exps/coeffs
// are 8-byte aligned per thread). Math identical to r15 (rel_err 1.8e-7).

#define A_DIM 256
#define P_DIM 6
#define BN_DIM (512 * 32)
#define ROWS_PER_BLOCK 16

__device__ __forceinline__ float ex2f(float x) {
    float r;
    asm("ex2.approx.f32 %0, %1;" : "=f"(r) : "f"(x));
    return r;
}

__global__ void __launch_bounds__(A_DIM, 4) aolayer_kernel(
    const float* __restrict__ pos,      // [BN, 3]
    const float* __restrict__ centers,  // [A, 3]
    const float* __restrict__ exps,     // [A, P]
    const float* __restrict__ coeffs,   // [A, P]
    const int*   __restrict__ powers,   // [A, 3]
    float* __restrict__ out)            // [BN, A]
{
    const int a = threadIdx.x;

    // ---- per-atom constants (once per block) ----
    const float ncx = -centers[a * 3 + 0];
    const float ncy = -centers[a * 3 + 1];
    const float ncz = -centers[a * 3 + 2];

    // exps/coeffs rows are 24 bytes/thread -> 8-byte aligned: float2 loads
    const float NEG_LOG2E = -1.4426950408889634f;
    float ep[P_DIM], co[P_DIM];
    {
        const float2* e2 = reinterpret_cast<const float2*>(exps + a * P_DIM);
        const float2* c2 = reinterpret_cast<const float2*>(coeffs + a * P_DIM);
#pragma unroll
        for (int h = 0; h < P_DIM / 2; h++) {
            const float2 ev = e2[h];
            const float2 cv = c2[h];
            ep[2 * h + 0] = ev.x * NEG_LOG2E;
            ep[2 * h + 1] = ev.y * NEG_LOG2E;
            co[2 * h + 0] = cv.x;
            co[2 * h + 1] = cv.y;
        }
    }

    const int px = powers[a * 3 + 0];
    const int py = powers[a * 3 + 1];
    const int pz = powers[a * 3 + 2];
    const bool lx = (px >= 1), qx = (px == 2);
    const bool ly = (py >= 1), qy = (py == 2);
    const bool lz = (pz >= 1), qz = (pz == 2);

    // ---- stage pos rows into shared memory ----
    __shared__ float spos[ROWS_PER_BLOCK * 3];
    const int row0 = blockIdx.x * ROWS_PER_BLOCK;
    if (threadIdx.x < ROWS_PER_BLOCK * 3) {
        spos[threadIdx.x] = pos[row0 * 3 + threadIdx.x];
    }
    __syncthreads();

    // ---- phase 1: all rows' r2 and angular (d dies immediately) ----
    float r2v[ROWS_PER_BLOCK];
    float angv[ROWS_PER_BLOCK];
#pragma unroll
    for (int r = 0; r < ROWS_PER_BLOCK; r++) {
        const float dx = spos[r * 3 + 0] + ncx;
        const float dy = spos[r * 3 + 1] + ncy;
        const float dz = spos[r * 3 + 2] + ncz;

        r2v[r] = fmaf(dx, dx, fmaf(dy, dy, dz * dz));

        float t = lx ? dx : 1.0f;
        if (qx) t *= dx;
        if (ly) t *= dy;
        if (qy) t *= dy;
        if (lz) t *= dz;
        if (qz) t *= dz;
        angv[r] = t;
    }

    float* out_base = out + (size_t)row0 * A_DIM + a;

    // ---- phase 2: dense EX2 stream; 6 independent triples per row ----
#pragma unroll
    for (int r = 0; r < ROWS_PER_BLOCK; r++) {
        const float r2 = r2v[r];
        float rad0 = co[0] * ex2f(ep[0] * r2);
        float rad1 = co[1] * ex2f(ep[1] * r2);
        rad0 = fmaf(co[2], ex2f(ep[2] * r2), rad0);
        rad1 = fmaf(co[3], ex2f(ep[3] * r2), rad1);
        rad0 = fmaf(co[4], ex2f(ep[4] * r2), rad0);
        rad1 = fmaf(co[5], ex2f(ep[5] * r2), rad1);

        out_base[r * A_DIM] = angv[r] * (rad0 + rad1);
    }
}

extern "C" void kernel_launch(void* const* d_in, const int* in_sizes, int n_in,
                              void* d_out, int out_size) {
    const float* pos     = (const float*)d_in[0];
    const float* centers = (const float*)d_in[1];
    const float* exps    = (const float*)d_in[2];
    const float* coeffs  = (const float*)d_in[3];
    const int*   powers  = (const int*)d_in[4];
    float* out = (float*)d_out;

    dim3 grid(BN_DIM / ROWS_PER_BLOCK);  // 1024 blocks
    dim3 block(A_DIM);                   // 256 threads, one per atom
    aolayer_kernel<<<grid, block>>>(pos, centers, exps, coeffs, powers, out);
}